// round 16
// baseline (speedup 1.0000x reference)
#include <cuda_runtime.h>
#include <math.h>
#include <stdint.h>

#define NK   4096
#define D    256
#define NIN  32768
#define BM   128
#define BN   128
#define CPAIRS 16
#define NTILES (NIN / BM)        // 256
#define CAP  128
#define DELTA 5.5e-4f
#define SX_ROWS 64

#define SCALE_X 21.166666666666668f     // 127/6
#define SCALE_W 520192.0f               // 127*4096
#define INV2    1.8164131e-07f          // 2/(SCALE_X*SCALE_W)

#define SMI_TOTAL (3 * 32768)

// ------------------------------- device scratch ----------------------------
__device__ float    g_sw[NK];
__device__ float    g_sx[NIN];
__device__ int      g_counts[NK];
__device__ float    g_partial[NTILES];
__device__ uint32_t g_XqT[NIN * 64];      // per 128-row tile: [64 d4][128 rows]
__device__ uint32_t g_WqT[NK * 64];       // per 128-code chunk: [64 d4][128 codes]
__device__ int      g_cand[NIN * CAP];
__device__ float    g_cscore[NIN * CAP];
__device__ int      g_ncand[NIN];
__device__ uint32_t g_rowmin[NIN];        // order-encoded float
__device__ int      g_tdone[NTILES];
__device__ unsigned g_gdone;

// ------------------------------- helpers -----------------------------------
__device__ __forceinline__ uint32_t smem_u32(const void* p) {
    uint32_t a;
    asm("{ .reg .u64 t; cvta.to.shared.u64 t, %1; cvt.u32.u64 %0, t; }"
        : "=r"(a) : "l"(p));
    return a;
}
__device__ __forceinline__ void cp16(uint32_t dst, const void* src) {
    asm volatile("cp.async.cg.shared.global [%0], [%1], 16;" :: "r"(dst), "l"(src));
}
#define CP_COMMIT() asm volatile("cp.async.commit_group;" ::: "memory")
#define CP_WAIT(n)  asm volatile("cp.async.wait_group %0;" :: "n"(n) : "memory")

__device__ __forceinline__ uint32_t fenc(float f) {
    int b = __float_as_int(f);
    return (b >= 0) ? ((uint32_t)b | 0x80000000u) : ~(uint32_t)b;
}
__device__ __forceinline__ float fdec(uint32_t u) {
    return (u & 0x80000000u) ? __int_as_float((int)(u & 0x7FFFFFFFu))
                             : __int_as_float((int)~u);
}
__device__ __forceinline__ uint32_t quant4(float a, float b, float c, float d, float s) {
    int q0 = __float2int_rn(fminf(fmaxf(a * s, -127.f), 127.f));
    int q1 = __float2int_rn(fminf(fmaxf(b * s, -127.f), 127.f));
    int q2 = __float2int_rn(fminf(fmaxf(c * s, -127.f), 127.f));
    int q3 = __float2int_rn(fminf(fmaxf(d * s, -127.f), 127.f));
    return (uint32_t)(q0 & 0xFF) | ((uint32_t)(q1 & 0xFF) << 8)
         | ((uint32_t)(q2 & 0xFF) << 16) | ((uint32_t)(q3 & 0xFF) << 24);
}

// exact dot, reference-order chain; unroll-4 keeps live regs bounded
__device__ __forceinline__ float dot_exact(const float* __restrict__ xr,
                                           const float* __restrict__ wr) {
    const float4* x4 = (const float4*)xr;
    const float4* w4 = (const float4*)wr;
    float acc = 0.f;
    #pragma unroll 4
    for (int i = 0; i < 64; i++) {
        float4 xv = __ldg(x4 + i), wv = __ldg(w4 + i);
        acc = fmaf(xv.x, wv.x, acc);
        acc = fmaf(xv.y, wv.y, acc);
        acc = fmaf(xv.z, wv.z, acc);
        acc = fmaf(xv.w, wv.w, acc);
    }
    return acc;
}

// --------------------------- fused prep kernel -----------------------------
__global__ void __launch_bounds__(256, 1)
k_prep(const float* __restrict__ W, const float* __restrict__ X) {
    int tid = threadIdx.x;
    if (blockIdx.x < 32) {
        __shared__ uint32_t t[128 * 65];
        int chunk = blockIdx.x;
        int gt = chunk * 256 + tid;
        if (gt < NK) g_counts[gt] = 0;
        if (gt < NTILES) g_tdone[gt] = 0;
        if (gt == 0) g_gdone = 0;
        {
            int row = tid >> 1, half = tid & 1;
            const float4* w4 = (const float4*)(W + (size_t)(chunk * 128 + row) * D) + half * 32;
            float s = 0.f;
            #pragma unroll 8
            for (int i = 0; i < 32; i++) {
                float4 v = w4[i];
                s += v.x*v.x + v.y*v.y + v.z*v.z + v.w*v.w;
            }
            s += __shfl_xor_sync(0xffffffffu, s, 1);
            if (half == 0) g_sw[chunk * 128 + row] = s;
        }
        for (int idx = tid; idx < 128 * 64; idx += 256) {
            int code = idx >> 6, d4 = idx & 63;
            const float4 v = *(const float4*)(W + (size_t)(chunk * 128 + code) * D + d4 * 4);
            t[code * 65 + d4] = quant4(v.x, v.y, v.z, v.w, SCALE_W);
        }
        __syncthreads();
        for (int idx = tid; idx < 128 * 64; idx += 256) {
            int d4 = idx >> 7, c = idx & 127;
            g_WqT[(size_t)chunk * 8192 + d4 * 128 + c] = t[c * 65 + d4];
        }
    } else {
        __shared__ float tile[SX_ROWS * 257];
        int xb = blockIdx.x - 32;
        int row0 = xb * SX_ROWS;
        int gt = xb * 256 + tid;
        if (gt < NIN) { g_ncand[gt] = 0; g_rowmin[gt] = 0xFFFFFFFFu; }
        {
            const float4* Xg = (const float4*)(X + (size_t)row0 * D);
            #pragma unroll
            for (int t4 = 0; t4 < 16; t4++) {
                int idx = tid + t4 * 256;
                int r = idx >> 6, c4 = (idx & 63) * 4;
                float4 v = Xg[idx];
                float* p = tile + r * 257 + c4;
                p[0] = v.x; p[1] = v.y; p[2] = v.z; p[3] = v.w;
            }
        }
        __syncthreads();
        if (tid < SX_ROWS) {
            // ref-exact sequential sum(x^2): XLA-CPU strict-IEEE scalar chain
            const float* p = tile + tid * 257;
            float s = 0.f;
            #pragma unroll 8
            for (int i = 0; i < D; i++) {
                float v = p[i];
                s = __fadd_rn(s, __fmul_rn(v, v));
            }
            g_sx[row0 + tid] = s;
        }
        int rt = row0 >> 7, rl0 = row0 & 127;
        for (int idx = tid; idx < SX_ROWS * 64; idx += 256) {
            int r = idx & 63, d4 = idx >> 6;
            const float* p = tile + r * 257 + d4 * 4;
            g_XqT[(size_t)rt * 8192 + d4 * 128 + rl0 + r] =
                quant4(p[0], p[1], p[2], p[3], SCALE_X);
        }
    }
}

// ------ pass 1: dp4a filter + ticketed tail (rescore/gather/finalize) ------
__global__ void __launch_bounds__(256, 2)
k_filter(const float* __restrict__ X, const float* __restrict__ W,
         float* __restrict__ out, int out_size) {
    extern __shared__ uint32_t smem[];
    uint32_t* Xs = smem;                        // [64][128]
    uint32_t* Wb[2] = { smem + 8192, smem + 16384 };
    __shared__ int s_done;
    __shared__ unsigned s_g;
    __shared__ float wsum[8];

    int tid = threadIdx.x;
    int rt = blockIdx.x >> 4, cp = blockIdx.x & (CPAIRS - 1);
    int row0 = rt * BM;

    {
        uint32_t xb = smem_u32(Xs);
        const char* xs = (const char*)(g_XqT + (size_t)rt * 8192);
        #pragma unroll
        for (int i = 0; i < 8; i++) { int idx = tid + i * 256; cp16(xb + idx * 16, xs + idx * 16); }
        uint32_t w0 = smem_u32(Wb[0]);
        const char* ws0 = (const char*)(g_WqT + (size_t)(cp * 2) * 8192);
        #pragma unroll
        for (int i = 0; i < 8; i++) { int idx = tid + i * 256; cp16(w0 + idx * 16, ws0 + idx * 16); }
        CP_COMMIT();
        uint32_t w1 = smem_u32(Wb[1]);
        const char* ws1 = ws0 + 32768;
        #pragma unroll
        for (int i = 0; i < 8; i++) { int idx = tid + i * 256; cp16(w1 + idx * 16, ws1 + idx * 16); }
        CP_COMMIT();
    }

    int tx = tid & 15, ty = tid >> 4;
    float lm[8];
    #pragma unroll
    for (int j = 0; j < 8; j++) lm[j] = 3.4e38f;

    CP_WAIT(1);
    __syncthreads();

    #pragma unroll
    for (int ch = 0; ch < 2; ch++) {
        const uint32_t* Wp = Wb[ch];
        int kbase = cp * 256 + ch * BN;

        int acc[8][8];
        #pragma unroll
        for (int j = 0; j < 8; j++)
            #pragma unroll
            for (int c = 0; c < 8; c++) acc[j][c] = 0;

        #pragma unroll 4
        for (int d4 = 0; d4 < 64; d4++) {
            uint4 a0 = *(const uint4*)(Xs + d4 * 128 + ty * 8);
            uint4 a1 = *(const uint4*)(Xs + d4 * 128 + ty * 8 + 4);
            uint4 b0 = *(const uint4*)(Wp + d4 * 128 + tx * 4);
            uint4 b1 = *(const uint4*)(Wp + d4 * 128 + 64 + tx * 4);
            uint32_t av[8] = {a0.x, a0.y, a0.z, a0.w, a1.x, a1.y, a1.z, a1.w};
            uint32_t bv[8] = {b0.x, b0.y, b0.z, b0.w, b1.x, b1.y, b1.z, b1.w};
            #pragma unroll
            for (int j = 0; j < 8; j++)
                #pragma unroll
                for (int c = 0; c < 8; c++)
                    acc[j][c] = __dp4a((int)av[j], (int)bv[c], acc[j][c]);
        }

        #pragma unroll
        for (int j = 0; j < 8; j++) {
            int row = row0 + ty * 8 + j;
            float s[8];
            float m = 3.4e38f;
            #pragma unroll
            for (int c = 0; c < 8; c++) {
                int k = kbase + ((c < 4) ? (tx * 4 + c) : (64 + tx * 4 + c - 4));
                s[c] = fmaf(-INV2, (float)acc[j][c], __ldg(&g_sw[k]));
                m = fminf(m, s[c]);
            }
            #pragma unroll
            for (int off = 8; off; off >>= 1)
                m = fminf(m, __shfl_xor_sync(0xffffffffu, m, off, 16));
            lm[j] = fminf(lm[j], m);
            float gm = fdec(g_rowmin[row]);      // racy read: conservative
            float thr = fminf(lm[j], gm) + DELTA;
            #pragma unroll
            for (int c = 0; c < 8; c++) {
                if (s[c] < thr) {
                    int k = kbase + ((c < 4) ? (tx * 4 + c) : (64 + tx * 4 + c - 4));
                    int slot = atomicAdd(&g_ncand[row], 1);
                    if (slot < CAP) {
                        g_cand[row * CAP + slot] = k;
                        g_cscore[row * CAP + slot] = s[c];
                    }
                }
            }
            if (tx == 0) atomicMin(&g_rowmin[row], fenc(lm[j]));
        }

        if (ch == 0) { CP_WAIT(0); __syncthreads(); }
    }

    // ---------------- tile ticket: last CTA of tile runs the tail ----------
    __threadfence();
    __syncthreads();
    if (tid == 0) s_done = atomicAdd(&g_tdone[rt], 1);
    __syncthreads();
    if (s_done != CPAIRS - 1) return;
    __threadfence();

    // tail: exact argmin + gather + loss partial for rows [row0, row0+128)
    int lane = tid & 31, warp = tid >> 5;
    float wls = 0.f;                 // lane partial of this warp's loss sum
    for (int rr = 0; rr < 16; rr++) {
        int row = row0 + warp * 16 + rr;
        int n = g_ncand[row];
        const float* xr = X + (size_t)row * D;
        int k;
        if (n <= CAP) {
            float thr = fdec(g_rowmin[row]) + DELTA;
            int mycnt = 0, myk = -1;
            for (int c = lane; c < n; c += 32) {
                if (g_cscore[row * CAP + c] < thr) { mycnt++; myk = g_cand[row * CAP + c]; }
            }
            int tot = mycnt;
            #pragma unroll
            for (int off = 16; off; off >>= 1) tot += __shfl_xor_sync(0xffffffffu, tot, off);
            if (tot == 1) {
                int kk = myk;
                #pragma unroll
                for (int off = 16; off; off >>= 1)
                    kk = max(kk, __shfl_xor_sync(0xffffffffu, kk, off));
                k = kk;
            } else {
                float sx = g_sx[row];
                unsigned long long best = 0xFFFFFFFFFFFFFFFFull;
                for (int c = lane; c < n; c += 32) {
                    if (g_cscore[row * CAP + c] < thr) {
                        int kc = g_cand[row * CAP + c];
                        float acc = dot_exact(xr, W + (size_t)kc * D);
                        float dd = __fsub_rn(__fadd_rn(sx, g_sw[kc]), __fmul_rn(2.0f, acc));
                        unsigned long long key =
                            ((unsigned long long)__float_as_uint(dd) << 32) | (unsigned)kc;
                        if (key < best) best = key;
                    }
                }
                #pragma unroll
                for (int off = 16; off; off >>= 1) {
                    unsigned long long o = __shfl_xor_sync(0xffffffffu, best, off);
                    if (o < best) best = o;
                }
                k = (int)(best & 0xffffffffu);
            }
        } else {  // overflow fallback: exact full scan (same deterministic answer)
            float sx = g_sx[row];
            unsigned long long best = 0xFFFFFFFFFFFFFFFFull;
            for (int base = 0; base < NK; base += 32) {
                int kc = base + lane;
                float acc = dot_exact(xr, W + (size_t)kc * D);
                float dd = __fsub_rn(__fadd_rn(sx, g_sw[kc]), __fmul_rn(2.0f, acc));
                unsigned long long key =
                    ((unsigned long long)__float_as_uint(dd) << 32) | (unsigned)kc;
                if (key < best) best = key;
            }
            #pragma unroll
            for (int off = 16; off; off >>= 1) {
                unsigned long long o = __shfl_xor_sync(0xffffffffu, best, off);
                if (o < best) best = o;
            }
            k = (int)(best & 0xffffffffu);
        }

        if (lane == 0) atomicAdd(&g_counts[k], 1);

        // gather: quantized_st = fl(x + fl(q - x)), loss partial
        const float4* wp = (const float4*)(W + (size_t)k * D);
        const float4* xp = (const float4*)xr;
        float* op = out + 1 + (size_t)row * D;
        #pragma unroll
        for (int i = lane; i < D / 4; i += 32) {
            float4 w = wp[i], x = xp[i];
            float dx = __fsub_rn(w.x, x.x), dy = __fsub_rn(w.y, x.y);
            float dz = __fsub_rn(w.z, x.z), dw = __fsub_rn(w.w, x.w);
            op[i * 4 + 0] = __fadd_rn(x.x, dx);
            op[i * 4 + 1] = __fadd_rn(x.y, dy);
            op[i * 4 + 2] = __fadd_rn(x.z, dz);
            op[i * 4 + 3] = __fadd_rn(x.w, dw);
            wls += dx * dx + dy * dy + dz * dz + dw * dw;
        }
    }
    #pragma unroll
    for (int off = 16; off; off >>= 1) wls += __shfl_down_sync(0xffffffffu, wls, off);
    if (lane == 0) wsum[warp] = wls;
    __syncthreads();
    if (tid == 0) {
        float t = 0.f;
        #pragma unroll
        for (int w = 0; w < 8; w++) t += wsum[w];
        g_partial[rt] = t;
        __threadfence();
        s_g = atomicAdd(&g_gdone, 1u);
    }
    __syncthreads();

    // ---------------- global ticket: last tile finalizes -------------------
    if (s_g == NTILES - 1) {
        __threadfence();
        float* red = (float*)smem;               // reuse dynamic smem
        float e = 0.f, ps = 0.f;
        for (int kk = tid; kk < NK; kk += 256) {
            float p = (float)g_counts[kk] * (1.0f / (float)NIN);
            e += p * logf(p + 1e-10f);
        }
        for (int b = tid; b < NTILES; b += 256) ps += g_partial[b];
        red[tid] = e;
        __syncthreads();
        for (int off = 128; off; off >>= 1) {
            if (tid < off) red[tid] += red[tid + off];
            __syncthreads();
        }
        float etot = red[0];
        __syncthreads();
        red[tid] = ps;
        __syncthreads();
        for (int off = 128; off; off >>= 1) {
            if (tid < off) red[tid] += red[tid + off];
            __syncthreads();
        }
        if (tid == 0) {
            out[0] = 1.25f * red[0] / (float)(NIN * D);
            out[out_size - 1] = expf(-etot);
        }
    }
}

// ---------------------------------------------------------------------------
extern "C" void kernel_launch(void* const* d_in, const int* in_sizes, int n_in,
                              void* d_out, int out_size) {
    const float* X = (const float*)d_in[0];
    const float* W = (const float*)d_in[1];
    float* out = (float*)d_out;

    cudaFuncSetAttribute((const void*)k_filter,
                         cudaFuncAttributeMaxDynamicSharedMemorySize, SMI_TOTAL);

    k_prep<<<32 + NIN / SX_ROWS, 256>>>(W, X);
    k_filter<<<NTILES * CPAIRS, 256, SMI_TOTAL>>>(X, W, out, out_size);
}

// round 17
// speedup vs baseline: 1.1491x; 1.1491x over previous
#include <cuda_runtime.h>
#include <math.h>
#include <stdint.h>

#define NK   4096
#define D    256
#define NIN  32768
#define BM   128
#define BN   128
#define CPAIRS 16
#define CAP  128
#define DELTA 5.5e-4f
#define RG_BLOCKS 4096
#define SX_ROWS 64

#define SCALE_X 21.166666666666668f     // 127/6
#define SCALE_W 520192.0f               // 127*4096
#define INV2    1.8164131e-07f          // 2/(SCALE_X*SCALE_W)

#define SMI_TOTAL (3 * 32768)

// ------------------------------- device scratch ----------------------------
__device__ float    g_sw[NK];
__device__ float    g_sx[NIN];
__device__ int      g_idx[NIN];
__device__ int      g_counts[NK];
__device__ float    g_partial[RG_BLOCKS];
__device__ uint32_t g_XqT[NIN * 64];      // per 128-row tile: [64 d4][128 rows]
__device__ uint32_t g_WqT[NK * 64];       // per 128-code chunk: [64 d4][128 codes]
__device__ int      g_cand[NIN * CAP];
__device__ float    g_cscore[NIN * CAP];
__device__ int      g_ncand[NIN];
__device__ uint32_t g_rowmin[NIN];        // order-encoded float

// ------------------------------- helpers -----------------------------------
__device__ __forceinline__ uint32_t smem_u32(const void* p) {
    uint32_t a;
    asm("{ .reg .u64 t; cvta.to.shared.u64 t, %1; cvt.u32.u64 %0, t; }"
        : "=r"(a) : "l"(p));
    return a;
}
__device__ __forceinline__ void cp16(uint32_t dst, const void* src) {
    asm volatile("cp.async.cg.shared.global [%0], [%1], 16;" :: "r"(dst), "l"(src));
}
#define CP_COMMIT() asm volatile("cp.async.commit_group;" ::: "memory")
#define CP_WAIT(n)  asm volatile("cp.async.wait_group %0;" :: "n"(n) : "memory")

__device__ __forceinline__ uint32_t fenc(float f) {
    int b = __float_as_int(f);
    return (b >= 0) ? ((uint32_t)b | 0x80000000u) : ~(uint32_t)b;
}
__device__ __forceinline__ float fdec(uint32_t u) {
    return (u & 0x80000000u) ? __int_as_float((int)(u & 0x7FFFFFFFu))
                             : __int_as_float((int)~u);
}
__device__ __forceinline__ uint32_t quant4(float a, float b, float c, float d, float s) {
    int q0 = __float2int_rn(fminf(fmaxf(a * s, -127.f), 127.f));
    int q1 = __float2int_rn(fminf(fmaxf(b * s, -127.f), 127.f));
    int q2 = __float2int_rn(fminf(fmaxf(c * s, -127.f), 127.f));
    int q3 = __float2int_rn(fminf(fmaxf(d * s, -127.f), 127.f));
    return (uint32_t)(q0 & 0xFF) | ((uint32_t)(q1 & 0xFF) << 8)
         | ((uint32_t)(q2 & 0xFF) << 16) | ((uint32_t)(q3 & 0xFF) << 24);
}

// exact dot, reference-order chain; unroll-4 keeps live regs bounded
__device__ __forceinline__ float dot_exact(const float* __restrict__ xr,
                                           const float* __restrict__ wr) {
    const float4* x4 = (const float4*)xr;
    const float4* w4 = (const float4*)wr;
    float acc = 0.f;
    #pragma unroll 4
    for (int i = 0; i < 64; i++) {
        float4 xv = __ldg(x4 + i), wv = __ldg(w4 + i);
        acc = fmaf(xv.x, wv.x, acc);
        acc = fmaf(xv.y, wv.y, acc);
        acc = fmaf(xv.z, wv.z, acc);
        acc = fmaf(xv.w, wv.w, acc);
    }
    return acc;
}

// --------------------------- fused prep kernel -----------------------------
// blocks [0,32): W chunks (sw + quantize transposed + zero counts)
// blocks [32,544): X tiles of 64 rows (ref-exact sx + quantize transposed)
__global__ void __launch_bounds__(256, 1)
k_prep(const float* __restrict__ W, const float* __restrict__ X) {
    int tid = threadIdx.x;
    if (blockIdx.x < 32) {
        __shared__ uint32_t t[128 * 65];
        int chunk = blockIdx.x;
        int gt = chunk * 256 + tid;
        if (gt < NK) g_counts[gt] = 0;
        {
            int row = tid >> 1, half = tid & 1;
            const float4* w4 = (const float4*)(W + (size_t)(chunk * 128 + row) * D) + half * 32;
            float s = 0.f;
            #pragma unroll 8
            for (int i = 0; i < 32; i++) {
                float4 v = w4[i];
                s += v.x*v.x + v.y*v.y + v.z*v.z + v.w*v.w;
            }
            s += __shfl_xor_sync(0xffffffffu, s, 1);
            if (half == 0) g_sw[chunk * 128 + row] = s;
        }
        for (int idx = tid; idx < 128 * 64; idx += 256) {
            int code = idx >> 6, d4 = idx & 63;
            const float4 v = *(const float4*)(W + (size_t)(chunk * 128 + code) * D + d4 * 4);
            t[code * 65 + d4] = quant4(v.x, v.y, v.z, v.w, SCALE_W);
        }
        __syncthreads();
        for (int idx = tid; idx < 128 * 64; idx += 256) {
            int d4 = idx >> 7, c = idx & 127;
            g_WqT[(size_t)chunk * 8192 + d4 * 128 + c] = t[c * 65 + d4];
        }
    } else {
        __shared__ float tile[SX_ROWS * 257];
        int xb = blockIdx.x - 32;
        int row0 = xb * SX_ROWS;
        int gt = xb * 256 + tid;
        if (gt < NIN) { g_ncand[gt] = 0; g_rowmin[gt] = 0xFFFFFFFFu; }
        // vectorized global loads, scalar smem stores (keeps 257-stride layout)
        {
            const float4* Xg = (const float4*)(X + (size_t)row0 * D);
            #pragma unroll
            for (int t4 = 0; t4 < 16; t4++) {
                int idx = tid + t4 * 256;           // 4096 float4s
                int r = idx >> 6, c4 = (idx & 63) * 4;
                float4 v = Xg[idx];
                float* p = tile + r * 257 + c4;
                p[0] = v.x; p[1] = v.y; p[2] = v.z; p[3] = v.w;
            }
        }
        __syncthreads();
        if (tid < SX_ROWS) {
            // ref-exact sequential sum(x^2): XLA-CPU strict-IEEE scalar chain
            const float* p = tile + tid * 257;
            float s = 0.f;
            #pragma unroll 8
            for (int i = 0; i < D; i++) {
                float v = p[i];
                s = __fadd_rn(s, __fmul_rn(v, v));
            }
            g_sx[row0 + tid] = s;
        }
        int rt = row0 >> 7, rl0 = row0 & 127;
        for (int idx = tid; idx < SX_ROWS * 64; idx += 256) {
            int r = idx & 63, d4 = idx >> 6;
            const float* p = tile + r * 257 + d4 * 4;
            g_XqT[(size_t)rt * 8192 + d4 * 128 + rl0 + r] =
                quant4(p[0], p[1], p[2], p[3], SCALE_X);
        }
    }
}

// -------------- pass 1: dp4a int8 GEMM + candidate filter ------------------
__global__ void __launch_bounds__(256, 2)
k_filter() {
    extern __shared__ uint32_t smem[];
    uint32_t* Xs = smem;                        // [64][128]
    uint32_t* Wb[2] = { smem + 8192, smem + 16384 };

    int tid = threadIdx.x;
    int rt = blockIdx.x >> 4, cp = blockIdx.x & (CPAIRS - 1);
    int row0 = rt * BM;

    {
        uint32_t xb = smem_u32(Xs);
        const char* xs = (const char*)(g_XqT + (size_t)rt * 8192);
        #pragma unroll
        for (int i = 0; i < 8; i++) { int idx = tid + i * 256; cp16(xb + idx * 16, xs + idx * 16); }
        uint32_t w0 = smem_u32(Wb[0]);
        const char* ws0 = (const char*)(g_WqT + (size_t)(cp * 2) * 8192);
        #pragma unroll
        for (int i = 0; i < 8; i++) { int idx = tid + i * 256; cp16(w0 + idx * 16, ws0 + idx * 16); }
        CP_COMMIT();
        uint32_t w1 = smem_u32(Wb[1]);
        const char* ws1 = ws0 + 32768;
        #pragma unroll
        for (int i = 0; i < 8; i++) { int idx = tid + i * 256; cp16(w1 + idx * 16, ws1 + idx * 16); }
        CP_COMMIT();
    }

    int tx = tid & 15, ty = tid >> 4;
    float lm[8];
    #pragma unroll
    for (int j = 0; j < 8; j++) lm[j] = 3.4e38f;

    CP_WAIT(1);
    __syncthreads();

    #pragma unroll
    for (int ch = 0; ch < 2; ch++) {
        const uint32_t* Wp = Wb[ch];
        int kbase = cp * 256 + ch * BN;

        int acc[8][8];
        #pragma unroll
        for (int j = 0; j < 8; j++)
            #pragma unroll
            for (int c = 0; c < 8; c++) acc[j][c] = 0;

        #pragma unroll 4
        for (int d4 = 0; d4 < 64; d4++) {
            uint4 a0 = *(const uint4*)(Xs + d4 * 128 + ty * 8);
            uint4 a1 = *(const uint4*)(Xs + d4 * 128 + ty * 8 + 4);
            uint4 b0 = *(const uint4*)(Wp + d4 * 128 + tx * 4);
            uint4 b1 = *(const uint4*)(Wp + d4 * 128 + 64 + tx * 4);
            uint32_t av[8] = {a0.x, a0.y, a0.z, a0.w, a1.x, a1.y, a1.z, a1.w};
            uint32_t bv[8] = {b0.x, b0.y, b0.z, b0.w, b1.x, b1.y, b1.z, b1.w};
            #pragma unroll
            for (int j = 0; j < 8; j++)
                #pragma unroll
                for (int c = 0; c < 8; c++)
                    acc[j][c] = __dp4a((int)av[j], (int)bv[c], acc[j][c]);
        }

        // hoist sw values: identical across the 8-row loop
        float swv[8];
        int kk8[8];
        #pragma unroll
        for (int c = 0; c < 8; c++) {
            kk8[c] = kbase + ((c < 4) ? (tx * 4 + c) : (64 + tx * 4 + c - 4));
            swv[c] = __ldg(&g_sw[kk8[c]]);
        }

        #pragma unroll
        for (int j = 0; j < 8; j++) {
            int row = row0 + ty * 8 + j;
            float s[8];
            float m = 3.4e38f;
            #pragma unroll
            for (int c = 0; c < 8; c++) {
                s[c] = fmaf(-INV2, (float)acc[j][c], swv[c]);
                m = fminf(m, s[c]);
            }
            #pragma unroll
            for (int off = 8; off; off >>= 1)
                m = fminf(m, __shfl_xor_sync(0xffffffffu, m, off, 16));
            lm[j] = fminf(lm[j], m);
            float gm = fdec(g_rowmin[row]);      // racy read: conservative
            float thr = fminf(lm[j], gm) + DELTA;
            #pragma unroll
            for (int c = 0; c < 8; c++) {
                if (s[c] < thr) {
                    int slot = atomicAdd(&g_ncand[row], 1);
                    if (slot < CAP) {
                        g_cand[row * CAP + slot] = kk8[c];
                        g_cscore[row * CAP + slot] = s[c];
                    }
                }
            }
            if (tx == 0) atomicMin(&g_rowmin[row], fenc(lm[j]));
        }

        if (ch == 0) { CP_WAIT(0); __syncthreads(); }
    }
}

// ---- pass 2: exact argmin (bit-exact) + gather + loss partial, fused ------
__global__ void __launch_bounds__(256, 4)
k_rescore_gather(const float* __restrict__ X, const float* __restrict__ W,
                 float* __restrict__ out) {
    __shared__ float wsum[8];
    int lane = threadIdx.x & 31, warp = threadIdx.x >> 5;
    int row = blockIdx.x * 8 + warp;
    int n = g_ncand[row];
    const float* xr = X + (size_t)row * D;
    int k;

    if (n <= CAP) {
        float thr = fdec(g_rowmin[row]) + DELTA;
        int mycnt = 0, myk = -1;
        for (int c = lane; c < n; c += 32) {
            if (g_cscore[row * CAP + c] < thr) { mycnt++; myk = g_cand[row * CAP + c]; }
        }
        int tot = mycnt;
        #pragma unroll
        for (int off = 16; off; off >>= 1) tot += __shfl_xor_sync(0xffffffffu, tot, off);
        if (tot == 1) {
            int kk = myk;
            #pragma unroll
            for (int off = 16; off; off >>= 1)
                kk = max(kk, __shfl_xor_sync(0xffffffffu, kk, off));
            k = kk;
        } else {
            float sx = g_sx[row];
            unsigned long long best = 0xFFFFFFFFFFFFFFFFull;
            for (int c = lane; c < n; c += 32) {
                if (g_cscore[row * CAP + c] < thr) {
                    int kc = g_cand[row * CAP + c];
                    float acc = dot_exact(xr, W + (size_t)kc * D);
                    float dd = __fsub_rn(__fadd_rn(sx, g_sw[kc]), __fmul_rn(2.0f, acc));
                    unsigned long long key =
                        ((unsigned long long)__float_as_uint(dd) << 32) | (unsigned)kc;
                    if (key < best) best = key;
                }
            }
            #pragma unroll
            for (int off = 16; off; off >>= 1) {
                unsigned long long o = __shfl_xor_sync(0xffffffffu, best, off);
                if (o < best) best = o;
            }
            k = (int)(best & 0xffffffffu);
        }
    } else {  // overflow fallback: exact full scan (same deterministic answer)
        float sx = g_sx[row];
        unsigned long long best = 0xFFFFFFFFFFFFFFFFull;
        for (int base = 0; base < NK; base += 32) {
            int kc = base + lane;
            float acc = dot_exact(xr, W + (size_t)kc * D);
            float dd = __fsub_rn(__fadd_rn(sx, g_sw[kc]), __fmul_rn(2.0f, acc));
            unsigned long long key =
                ((unsigned long long)__float_as_uint(dd) << 32) | (unsigned)kc;
            if (key < best) best = key;
        }
        #pragma unroll
        for (int off = 16; off; off >>= 1) {
            unsigned long long o = __shfl_xor_sync(0xffffffffu, best, off);
            if (o < best) best = o;
        }
        k = (int)(best & 0xffffffffu);
    }

    if (lane == 0) { g_idx[row] = k; atomicAdd(&g_counts[k], 1); }

    // gather: quantized_st = fl(x + fl(q - x)), loss partial
    float s = 0.f;
    const float4* wp = (const float4*)(W + (size_t)k * D);
    const float4* xp = (const float4*)xr;
    float* op = out + 1 + (size_t)row * D;
    #pragma unroll
    for (int i = lane; i < D / 4; i += 32) {
        float4 w = wp[i], x = xp[i];
        float dx = __fsub_rn(w.x, x.x), dy = __fsub_rn(w.y, x.y);
        float dz = __fsub_rn(w.z, x.z), dw = __fsub_rn(w.w, x.w);
        op[i * 4 + 0] = __fadd_rn(x.x, dx);
        op[i * 4 + 1] = __fadd_rn(x.y, dy);
        op[i * 4 + 2] = __fadd_rn(x.z, dz);
        op[i * 4 + 3] = __fadd_rn(x.w, dw);
        s += dx * dx + dy * dy + dz * dz + dw * dw;
    }
    #pragma unroll
    for (int off = 16; off; off >>= 1) s += __shfl_down_sync(0xffffffffu, s, off);
    if (lane == 0) wsum[warp] = s;
    __syncthreads();
    if (threadIdx.x == 0) {
        float t = 0.f;
        #pragma unroll
        for (int w = 0; w < 8; w++) t += wsum[w];
        g_partial[blockIdx.x] = t;
    }
}

// ------------- finalize (1 block, 1024 threads, deterministic) -------------
__global__ void __launch_bounds__(1024, 1)
k_final(float* __restrict__ out, int out_size) {
    __shared__ float red[1024];
    int tid = threadIdx.x;
    float e = 0.f, ps = 0.f;
    for (int kk = tid; kk < NK; kk += 1024) {
        float p = (float)g_counts[kk] * (1.0f / (float)NIN);
        e += p * logf(p + 1e-10f);
    }
    for (int b = tid; b < RG_BLOCKS; b += 1024) ps += g_partial[b];
    red[tid] = e;
    __syncthreads();
    for (int off = 512; off; off >>= 1) {
        if (tid < off) red[tid] += red[tid + off];
        __syncthreads();
    }
    float etot = red[0];
    __syncthreads();
    red[tid] = ps;
    __syncthreads();
    for (int off = 512; off; off >>= 1) {
        if (tid < off) red[tid] += red[tid + off];
        __syncthreads();
    }
    if (tid == 0) {
        out[0] = 1.25f * red[0] / (float)(NIN * D);
        out[out_size - 1] = expf(-etot);
    }
}

// ---------------------------------------------------------------------------
extern "C" void kernel_launch(void* const* d_in, const int* in_sizes, int n_in,
                              void* d_out, int out_size) {
    const float* X = (const float*)d_in[0];
    const float* W = (const float*)d_in[1];
    float* out = (float*)d_out;

    cudaFuncSetAttribute((const void*)k_filter,
                         cudaFuncAttributeMaxDynamicSharedMemorySize, SMI_TOTAL);

    k_prep<<<32 + NIN / SX_ROWS, 256>>>(W, X);
    k_filter<<<(NIN / BM) * CPAIRS, 256, SMI_TOTAL>>>();
    k_rescore_gather<<<RG_BLOCKS, 256>>>(X, W, out);
    k_final<<<1, 1024>>>(out, out_size);
}